// round 7
// baseline (speedup 1.0000x reference)
#include <cuda_runtime.h>
#include <cstdint>

// Problem constants (fixed by the dataset)
#define NE     1600000
#define D      128
#define TWO_D  256
#define SEG    50000

#define NEG_INF __int_as_float(0xFF800000)

#define N_RED_ITEMS 6250            // 8 segments per item -> 50000 segments
#define N_TILES     391             // ceil(50000 / 128) gemm row tiles
#define N_ITEMS     (N_RED_ITEMS + N_TILES)

// Scratch: device globals (no cudaMalloc allowed). Zero at module load;
// scan_kernel re-zeroes g_cnt / g_work / g_done each replay (it runs earlier
// in stream order than their consumers).
static __device__ int      g_cnt[SEG];                 // histogram (self-cleaning)
static __device__ int      g_offs[SEG + 1];            // exclusive offsets
static __device__ int      g_rank[NE];                 // per-edge rank within segment
static __device__ int      g_perm[NE];                 // edge ids grouped by segment
static __device__ float    g_cat[(size_t)SEG * TWO_D]; // [seg][0:128)=sum, [128:256)=max
static __device__ unsigned g_work;                     // persistent work counter
static __device__ int      g_done[N_TILES];            // rows completed per gemm tile

// ---------------------------------------------------------------------------
// Kernel 1: fused histogram + rank, 8 edges per thread.
// ---------------------------------------------------------------------------
__global__ void __launch_bounds__(256) hist_rank_kernel(const int* __restrict__ index) {
    int i = blockIdx.x * 256 + threadIdx.x;          // unit: 2 x int4 = 8 edges
    if (i < NE / 8) {
        int4 s0 = ((const int4*)index)[2 * i];
        int4 s1 = ((const int4*)index)[2 * i + 1];
        int4 r0, r1;
        r0.x = atomicAdd(&g_cnt[s0.x], 1);
        r0.y = atomicAdd(&g_cnt[s0.y], 1);
        r0.z = atomicAdd(&g_cnt[s0.z], 1);
        r0.w = atomicAdd(&g_cnt[s0.w], 1);
        r1.x = atomicAdd(&g_cnt[s1.x], 1);
        r1.y = atomicAdd(&g_cnt[s1.y], 1);
        r1.z = atomicAdd(&g_cnt[s1.z], 1);
        r1.w = atomicAdd(&g_cnt[s1.w], 1);
        ((int4*)g_rank)[2 * i]     = r0;
        ((int4*)g_rank)[2 * i + 1] = r1;
    }
}

// ---------------------------------------------------------------------------
// Kernel 2: exclusive scan of 50K counters; also resets g_cnt, g_work,
// g_done for the next replay. One block, 1024 threads.
// ---------------------------------------------------------------------------
__global__ void __launch_bounds__(1024) scan_kernel() {
    __shared__ int part[1024];
    const int CH = 49;                     // 1024*49 = 50176 >= 50000
    int t  = threadIdx.x;

    if (t < N_TILES) g_done[t] = 0;        // reset overlap state for this replay
    if (t == 0)      g_work    = 0;

    int lo = t * CH;
    int hi = lo + CH; if (hi > SEG) hi = SEG;
    if (lo > SEG) lo = SEG;

    int cnt[CH];
    int s = 0;
    for (int i = lo; i < hi; i++) { cnt[i - lo] = g_cnt[i]; s += cnt[i - lo]; }
    part[t] = s;
    __syncthreads();

    for (int off = 1; off < 1024; off <<= 1) {
        int v = 0;
        if (t >= off) v = part[t - off];
        __syncthreads();
        if (t >= off) part[t] += v;
        __syncthreads();
    }

    int run = (t == 0) ? 0 : part[t - 1];
    for (int i = lo; i < hi; i++) {
        g_offs[i] = run;
        g_cnt[i]  = 0;                     // self-clean for next replay
        run += cnt[i - lo];
    }
    if (t == 1023) g_offs[SEG] = part[1023];
}

// ---------------------------------------------------------------------------
// Kernel 3: atomic-free permutation scatter, 8 edges per thread.
// ---------------------------------------------------------------------------
__global__ void __launch_bounds__(256) perm_kernel(const int* __restrict__ index) {
    int i = blockIdx.x * 256 + threadIdx.x;
    if (i < NE / 8) {
        int4 s0 = ((const int4*)index)[2 * i];
        int4 s1 = ((const int4*)index)[2 * i + 1];
        int4 r0 = ((const int4*)g_rank)[2 * i];
        int4 r1 = ((const int4*)g_rank)[2 * i + 1];
        int e = i * 8;
        g_perm[__ldg(&g_offs[s0.x]) + r0.x] = e;
        g_perm[__ldg(&g_offs[s0.y]) + r0.y] = e + 1;
        g_perm[__ldg(&g_offs[s0.z]) + r0.z] = e + 2;
        g_perm[__ldg(&g_offs[s0.w]) + r0.w] = e + 3;
        g_perm[__ldg(&g_offs[s1.x]) + r1.x] = e + 4;
        g_perm[__ldg(&g_offs[s1.y]) + r1.y] = e + 5;
        g_perm[__ldg(&g_offs[s1.z]) + r1.z] = e + 6;
        g_perm[__ldg(&g_offs[s1.w]) + r1.w] = e + 7;
    }
}

// ---------------------------------------------------------------------------
// Kernel 4 (PERSISTENT): reduce items then gemm tiles from one ordered work
// queue, so the FFMA-bound GEMM executes in the issue slots left idle by the
// DRAM-bound reduce.
//   item < 6250 : reduce 8 segments (warp w -> segment item*8+w). Each warp,
//                 after storing its g_cat row: threadfence + done[seg/128]++.
//   item >= 6250: gemm tile (128 rows x 128 cols). Spin (acquire+nanosleep)
//                 until all its rows are done, then FFMA2 GEMM.
// Deadlock-free: counter hands out ALL reduce items before any gemm item;
// an owned reduce item always completes without waiting.
// ---------------------------------------------------------------------------
#define BM   128
#define BK   16
#define AMS  132   // As row stride (words)
#define BS2S 258   // Bs row stride (words, duplicated layout)

__global__ void __launch_bounds__(256, 2) persistent_kernel(const float* __restrict__ src,
                                                            const float* __restrict__ W,
                                                            const float* __restrict__ bias,
                                                            float* __restrict__ out) {
    __shared__ float As[BK * AMS];     // As[k][m]
    __shared__ float Bs[BK * BS2S];    // Bs[k][2d] = Bs[k][2d+1] = W[d][k]
    __shared__ unsigned s_item;

    int tid  = threadIdx.x;
    int w    = tid >> 5;
    int lane = tid & 31;

    while (true) {
        if (tid == 0) s_item = atomicAdd(&g_work, 1u);
        __syncthreads();
        unsigned it = s_item;
        __syncthreads();
        if (it >= N_ITEMS) return;

        if (it < N_RED_ITEMS) {
            // ---------------- reduce item: 8 segments, one per warp ----------------
            int seg   = (int)it * 8 + w;
            int start = __ldg(&g_offs[seg]);
            int end   = __ldg(&g_offs[seg + 1]);

            float4 sum = make_float4(0.f, 0.f, 0.f, 0.f);
            float4 mx  = make_float4(NEG_INF, NEG_INF, NEG_INF, NEG_INF);

            int i = start;
            for (; i + 7 < end; i += 8) {
                int e[8];
                #pragma unroll
                for (int j = 0; j < 8; j++) e[j] = __ldg(&g_perm[i + j]);
                float4 v[8];
                #pragma unroll
                for (int j = 0; j < 8; j++)
                    v[j] = __ldcs((const float4*)(src + (size_t)e[j] * D) + lane);
                #pragma unroll
                for (int j = 0; j < 8; j++) {
                    sum.x += v[j].x; sum.y += v[j].y; sum.z += v[j].z; sum.w += v[j].w;
                    mx.x = fmaxf(mx.x, v[j].x); mx.y = fmaxf(mx.y, v[j].y);
                    mx.z = fmaxf(mx.z, v[j].z); mx.w = fmaxf(mx.w, v[j].w);
                }
            }
            for (; i < end; i++) {
                int e0 = __ldg(&g_perm[i]);
                float4 v0 = __ldcs((const float4*)(src + (size_t)e0 * D) + lane);
                sum.x += v0.x; sum.y += v0.y; sum.z += v0.z; sum.w += v0.w;
                mx.x = fmaxf(mx.x, v0.x); mx.y = fmaxf(mx.y, v0.y);
                mx.z = fmaxf(mx.z, v0.z); mx.w = fmaxf(mx.w, v0.w);
            }
            if (start == end)             // torch_scatter: empty max = 0
                mx = make_float4(0.f, 0.f, 0.f, 0.f);

            size_t base = (size_t)seg * TWO_D + (size_t)lane * 4;
            *(float4*)(g_cat + base)     = sum;
            *(float4*)(g_cat + base + D) = mx;

            __threadfence();              // release the row before signaling
            if (lane == 0) atomicAdd(&g_done[seg >> 7], 1);
        } else {
            // ---------------- gemm tile: 128 rows x 128 cols ----------------
            int tile = (int)(it - N_RED_ITEMS);
            int row0 = tile * BM;
            int need = (SEG - row0 < BM) ? (SEG - row0) : BM;

            if (tid == 0) {
                while (true) {
                    int v;
                    asm volatile("ld.acquire.gpu.global.u32 %0, [%1];"
                                 : "=r"(v) : "l"(&g_done[tile]) : "memory");
                    if (v >= need) break;
                    __nanosleep(200);
                }
            }
            __syncthreads();
            __threadfence();              // ensure row data visible to all threads

            unsigned long long acc[8][4];
            #pragma unroll
            for (int p = 0; p < 8; p++)
                #pragma unroll
                for (int c = 0; c < 4; c++) acc[p][c] = 0ull;

            for (int kc = 0; kc < TWO_D; kc += BK) {
                #pragma unroll
                for (int l = 0; l < 2; l++) {
                    int idx = tid + l * 256;
                    int m   = idx >> 2;          // 0..127
                    int k4  = (idx & 3) * 4;     // 0,4,8,12
                    int gr  = row0 + m;
                    float4 v = make_float4(0.f, 0.f, 0.f, 0.f);
                    if (gr < SEG)
                        v = *(const float4*)(g_cat + (size_t)gr * TWO_D + kc + k4);
                    As[(k4 + 0) * AMS + m] = v.x;
                    As[(k4 + 1) * AMS + m] = v.y;
                    As[(k4 + 2) * AMS + m] = v.z;
                    As[(k4 + 3) * AMS + m] = v.w;
                }
                #pragma unroll
                for (int l = 0; l < 2; l++) {
                    int idx = tid + l * 256;
                    int d   = idx >> 2;          // 0..127
                    int k4  = (idx & 3) * 4;
                    float4 v = *(const float4*)(W + (size_t)d * TWO_D + kc + k4);
                    float vv[4] = {v.x, v.y, v.z, v.w};
                    #pragma unroll
                    for (int q = 0; q < 4; q++) {
                        unsigned long long dup;
                        asm("mov.b64 %0, {%1, %1};" : "=l"(dup) : "f"(vv[q]));
                        *(unsigned long long*)(Bs + (k4 + q) * BS2S + 2 * d) = dup;
                    }
                }
                __syncthreads();

                #pragma unroll
                for (int k = 0; k < BK; k++) {
                    unsigned long long ap[8];
                    #pragma unroll
                    for (int g = 0; g < 4; g++) {
                        ulonglong2 a2 = *(const ulonglong2*)(As + k * AMS + 16 * w + 4 * g);
                        ap[2 * g]     = a2.x;
                        ap[2 * g + 1] = a2.y;
                    }
                    unsigned long long bsr[4];
                    #pragma unroll
                    for (int c = 0; c < 4; c++)
                        bsr[c] = *(const unsigned long long*)(Bs + k * BS2S + 2 * (lane + 32 * c));

                    #pragma unroll
                    for (int p = 0; p < 8; p++)
                        #pragma unroll
                        for (int c = 0; c < 4; c++)
                            asm("fma.rn.f32x2 %0, %1, %2, %0;"
                                : "+l"(acc[p][c]) : "l"(ap[p]), "l"(bsr[c]));
                }
                __syncthreads();
            }

            float bb[4];
            #pragma unroll
            for (int c = 0; c < 4; c++) bb[c] = __ldg(bias + lane + 32 * c);

            #pragma unroll
            for (int p = 0; p < 8; p++) {
                int gr0 = row0 + 16 * w + 2 * p;
                #pragma unroll
                for (int c = 0; c < 4; c++) {
                    float r0, r1;
                    asm("mov.b64 {%0, %1}, %2;" : "=f"(r0), "=f"(r1) : "l"(acc[p][c]));
                    int col = lane + 32 * c;
                    if (gr0 < SEG)     out[(size_t)gr0 * D + col]       = r0 + bb[c];
                    if (gr0 + 1 < SEG) out[(size_t)(gr0 + 1) * D + col] = r1 + bb[c];
                }
            }
            __syncthreads();   // protect As/Bs before next item
        }
    }
}

// ---------------------------------------------------------------------------
// Launch pipeline: hist_rank -> scan(+reset) -> perm -> persistent(reduce+gemm)
// Inputs (metadata order): src[f32 NE*D], index[i32 NE], W[f32 D*2D], b[f32 D]
// ---------------------------------------------------------------------------
extern "C" void kernel_launch(void* const* d_in, const int* in_sizes, int n_in,
                              void* d_out, int out_size) {
    const float* src   = (const float*)d_in[0];
    const int*   index = (const int*)d_in[1];
    const float* W     = (const float*)d_in[2];
    const float* bias  = (const float*)d_in[3];
    float* out = (float*)d_out;

    (void)in_sizes; (void)n_in; (void)out_size;

    hist_rank_kernel<<<(NE / 8 + 255) / 256, 256>>>(index);
    scan_kernel<<<1, 1024>>>();
    perm_kernel<<<(NE / 8 + 255) / 256, 256>>>(index);
    persistent_kernel<<<296, 256>>>(src, W, bias, out);   // 2 blocks/SM x 148 SMs
}

// round 8
// speedup vs baseline: 1.0566x; 1.0566x over previous
#include <cuda_runtime.h>
#include <cstdint>

// Problem constants (fixed by the dataset)
#define NE     1600000
#define D      128
#define TWO_D  256
#define SEG    50000

#define NEG_INF __int_as_float(0xFF800000)

#define N_RED_ITEMS 6250            // 8 segments per item -> 50000 segments
#define BM          64              // gemm tile rows
#define N_TILES     782             // ceil(50000 / 64)
#define N_ITEMS     (N_RED_ITEMS + N_TILES)

// Scratch: device globals (no cudaMalloc allowed). Zero at module load;
// scan_kernel re-zeroes g_cnt / g_work / g_done each replay (it runs earlier
// in stream order than their consumers).
static __device__ int      g_cnt[SEG];                 // histogram (self-cleaning)
static __device__ int      g_offs[SEG + 1];            // exclusive offsets
static __device__ int      g_rank[NE];                 // per-edge rank within segment
static __device__ int      g_perm[NE];                 // edge ids grouped by segment
static __device__ float    g_cat[(size_t)SEG * TWO_D]; // [seg][0:128)=sum, [128:256)=max
static __device__ unsigned g_work;                     // persistent work counter
static __device__ int      g_done[N_TILES];            // rows completed per gemm tile

// ---------------------------------------------------------------------------
// Kernel 1: fused histogram + rank, 8 edges per thread.
// ---------------------------------------------------------------------------
__global__ void __launch_bounds__(256) hist_rank_kernel(const int* __restrict__ index) {
    int i = blockIdx.x * 256 + threadIdx.x;          // unit: 2 x int4 = 8 edges
    if (i < NE / 8) {
        int4 s0 = ((const int4*)index)[2 * i];
        int4 s1 = ((const int4*)index)[2 * i + 1];
        int4 r0, r1;
        r0.x = atomicAdd(&g_cnt[s0.x], 1);
        r0.y = atomicAdd(&g_cnt[s0.y], 1);
        r0.z = atomicAdd(&g_cnt[s0.z], 1);
        r0.w = atomicAdd(&g_cnt[s0.w], 1);
        r1.x = atomicAdd(&g_cnt[s1.x], 1);
        r1.y = atomicAdd(&g_cnt[s1.y], 1);
        r1.z = atomicAdd(&g_cnt[s1.z], 1);
        r1.w = atomicAdd(&g_cnt[s1.w], 1);
        ((int4*)g_rank)[2 * i]     = r0;
        ((int4*)g_rank)[2 * i + 1] = r1;
    }
}

// ---------------------------------------------------------------------------
// Kernel 2: exclusive scan of 50K counters (NO per-thread local array -> no
// local-memory spill). Also resets g_cnt, g_work, g_done for the next replay.
// ---------------------------------------------------------------------------
__global__ void __launch_bounds__(1024) scan_kernel() {
    __shared__ int part[1024];
    const int CH = 49;                     // 1024*49 = 50176 >= 50000
    int t = threadIdx.x;

    if (t == 0) g_work = 0;
    if (t < N_TILES) g_done[t] = 0;        // 782 < 1024: single pass

    int lo = t * CH; if (lo > SEG) lo = SEG;
    int hi = lo + CH; if (hi > SEG) hi = SEG;

    // pass 1: per-thread sum, fully unrolled predicated loads (high MLP)
    int s = 0;
    #pragma unroll
    for (int j = 0; j < CH; j++) {
        int idx = lo + j;
        if (idx < hi) s += g_cnt[idx];
    }
    part[t] = s;
    __syncthreads();

    // inclusive Hillis-Steele scan over 1024 partials
    for (int off = 1; off < 1024; off <<= 1) {
        int v = 0;
        if (t >= off) v = part[t - off];
        __syncthreads();
        if (t >= off) part[t] += v;
        __syncthreads();
    }

    // pass 2: re-read counters (L2-hot), emit offsets, zero counters
    int run = (t == 0) ? 0 : part[t - 1];
    for (int i = lo; i < hi; i++) {
        int c = g_cnt[i];
        g_offs[i] = run;
        g_cnt[i]  = 0;                     // self-clean for next replay
        run += c;
    }
    if (t == 1023) g_offs[SEG] = part[1023];
}

// ---------------------------------------------------------------------------
// Kernel 3: atomic-free permutation scatter, 8 edges per thread.
// ---------------------------------------------------------------------------
__global__ void __launch_bounds__(256) perm_kernel(const int* __restrict__ index) {
    int i = blockIdx.x * 256 + threadIdx.x;
    if (i < NE / 8) {
        int4 s0 = ((const int4*)index)[2 * i];
        int4 s1 = ((const int4*)index)[2 * i + 1];
        int4 r0 = ((const int4*)g_rank)[2 * i];
        int4 r1 = ((const int4*)g_rank)[2 * i + 1];
        int e = i * 8;
        g_perm[__ldg(&g_offs[s0.x]) + r0.x] = e;
        g_perm[__ldg(&g_offs[s0.y]) + r0.y] = e + 1;
        g_perm[__ldg(&g_offs[s0.z]) + r0.z] = e + 2;
        g_perm[__ldg(&g_offs[s0.w]) + r0.w] = e + 3;
        g_perm[__ldg(&g_offs[s1.x]) + r1.x] = e + 4;
        g_perm[__ldg(&g_offs[s1.y]) + r1.y] = e + 5;
        g_perm[__ldg(&g_offs[s1.z]) + r1.z] = e + 6;
        g_perm[__ldg(&g_offs[s1.w]) + r1.w] = e + 7;
    }
}

// ---------------------------------------------------------------------------
// Kernel 4 (PERSISTENT, <=64 regs): ordered work queue of reduce items then
// gemm tiles. The 64-reg cap keeps 4 blocks/SM (32 warps) so the DRAM-bound
// reduce phase retains gather occupancy while gemm tiles fill idle fma slots.
//   item < 6250 : reduce 8 segments (warp w -> segment item*8+w), then
//                 threadfence + done[seg/64]++ per warp.
//   item >= 6250: gemm tile (64 rows x 128 cols). Spin (acquire + nanosleep)
//                 until all rows done, then FFMA2 GEMM (row-pair packed).
// Deadlock-free: all reduce items are handed out before any gemm item.
// ---------------------------------------------------------------------------
#define BK   16
#define AMS  68    // As row stride (words): 64 + 4 pad
#define BS2S 258   // Bs row stride (words, duplicated layout)

__global__ void __launch_bounds__(256, 4) persistent_kernel(const float* __restrict__ src,
                                                            const float* __restrict__ W,
                                                            const float* __restrict__ bias,
                                                            float* __restrict__ out) {
    __shared__ float As[BK * AMS];     // As[k][m], m in [0,64)
    __shared__ float Bs[BK * BS2S];    // Bs[k][2d] = Bs[k][2d+1] = W[d][k]
    __shared__ unsigned s_item;

    int tid  = threadIdx.x;
    int w    = tid >> 5;
    int lane = tid & 31;

    while (true) {
        if (tid == 0) s_item = atomicAdd(&g_work, 1u);
        __syncthreads();
        unsigned it = s_item;
        __syncthreads();
        if (it >= N_ITEMS) return;

        if (it < N_RED_ITEMS) {
            // ---------------- reduce item: 8 segments, one per warp ----------------
            int seg   = (int)it * 8 + w;
            int start = __ldg(&g_offs[seg]);
            int end   = __ldg(&g_offs[seg + 1]);

            float4 sum = make_float4(0.f, 0.f, 0.f, 0.f);
            float4 mx  = make_float4(NEG_INF, NEG_INF, NEG_INF, NEG_INF);

            int i = start;
            for (; i + 7 < end; i += 8) {
                int e[8];
                #pragma unroll
                for (int j = 0; j < 8; j++) e[j] = __ldg(&g_perm[i + j]);
                float4 v[8];
                #pragma unroll
                for (int j = 0; j < 8; j++)
                    v[j] = __ldcs((const float4*)(src + (size_t)e[j] * D) + lane);
                #pragma unroll
                for (int j = 0; j < 8; j++) {
                    sum.x += v[j].x; sum.y += v[j].y; sum.z += v[j].z; sum.w += v[j].w;
                    mx.x = fmaxf(mx.x, v[j].x); mx.y = fmaxf(mx.y, v[j].y);
                    mx.z = fmaxf(mx.z, v[j].z); mx.w = fmaxf(mx.w, v[j].w);
                }
            }
            for (; i < end; i++) {
                int e0 = __ldg(&g_perm[i]);
                float4 v0 = __ldcs((const float4*)(src + (size_t)e0 * D) + lane);
                sum.x += v0.x; sum.y += v0.y; sum.z += v0.z; sum.w += v0.w;
                mx.x = fmaxf(mx.x, v0.x); mx.y = fmaxf(mx.y, v0.y);
                mx.z = fmaxf(mx.z, v0.z); mx.w = fmaxf(mx.w, v0.w);
            }
            if (start == end)             // torch_scatter: empty max = 0
                mx = make_float4(0.f, 0.f, 0.f, 0.f);

            size_t base = (size_t)seg * TWO_D + (size_t)lane * 4;
            *(float4*)(g_cat + base)     = sum;
            *(float4*)(g_cat + base + D) = mx;

            __threadfence();              // release the row before signaling
            if (lane == 0) atomicAdd(&g_done[seg >> 6], 1);
        } else {
            // ---------------- gemm tile: 64 rows x 128 cols ----------------
            int tile = (int)(it - N_RED_ITEMS);
            int row0 = tile * BM;
            int need = (SEG - row0 < BM) ? (SEG - row0) : BM;

            if (tid == 0) {
                while (true) {
                    int v;
                    asm volatile("ld.acquire.gpu.global.u32 %0, [%1];"
                                 : "=r"(v) : "l"(&g_done[tile]) : "memory");
                    if (v >= need) break;
                    __nanosleep(200);
                }
            }
            __syncthreads();

            unsigned long long acc[4][4];   // [row pair p][col c]
            #pragma unroll
            for (int p = 0; p < 4; p++)
                #pragma unroll
                for (int c = 0; c < 4; c++) acc[p][c] = 0ull;

            for (int kc = 0; kc < TWO_D; kc += BK) {
                // stage A: 64 m x 16 k = 256 float4, 1 per thread
                {
                    int m  = tid >> 2;           // 0..63
                    int k4 = (tid & 3) * 4;      // 0,4,8,12
                    int gr = row0 + m;
                    float4 v = make_float4(0.f, 0.f, 0.f, 0.f);
                    if (gr < SEG)
                        v = *(const float4*)(g_cat + (size_t)gr * TWO_D + kc + k4);
                    As[(k4 + 0) * AMS + m] = v.x;
                    As[(k4 + 1) * AMS + m] = v.y;
                    As[(k4 + 2) * AMS + m] = v.z;
                    As[(k4 + 3) * AMS + m] = v.w;
                }
                // stage B duplicated: 128 d x 16 k = 512 float4, 2 per thread
                #pragma unroll
                for (int l = 0; l < 2; l++) {
                    int idx = tid + l * 256;
                    int d   = idx >> 2;          // 0..127
                    int k4  = (idx & 3) * 4;
                    float4 v = *(const float4*)(W + (size_t)d * TWO_D + kc + k4);
                    float vv[4] = {v.x, v.y, v.z, v.w};
                    #pragma unroll
                    for (int q = 0; q < 4; q++) {
                        unsigned long long dup;
                        asm("mov.b64 %0, {%1, %1};" : "=l"(dup) : "f"(vv[q]));
                        *(unsigned long long*)(Bs + (k4 + q) * BS2S + 2 * d) = dup;
                    }
                }
                __syncthreads();

                #pragma unroll
                for (int k = 0; k < BK; k++) {
                    unsigned long long ap[4];
                    #pragma unroll
                    for (int g = 0; g < 2; g++) {
                        ulonglong2 a2 = *(const ulonglong2*)(As + k * AMS + 8 * w + 4 * g);
                        ap[2 * g]     = a2.x;
                        ap[2 * g + 1] = a2.y;
                    }
                    unsigned long long bsr[4];
                    #pragma unroll
                    for (int c = 0; c < 4; c++)
                        bsr[c] = *(const unsigned long long*)(Bs + k * BS2S + 2 * (lane + 32 * c));

                    #pragma unroll
                    for (int p = 0; p < 4; p++)
                        #pragma unroll
                        for (int c = 0; c < 4; c++)
                            asm("fma.rn.f32x2 %0, %1, %2, %0;"
                                : "+l"(acc[p][c]) : "l"(ap[p]), "l"(bsr[c]));
                }
                __syncthreads();
            }

            float bb[4];
            #pragma unroll
            for (int c = 0; c < 4; c++) bb[c] = __ldg(bias + lane + 32 * c);

            #pragma unroll
            for (int p = 0; p < 4; p++) {
                int gr0 = row0 + 8 * w + 2 * p;
                #pragma unroll
                for (int c = 0; c < 4; c++) {
                    float r0, r1;
                    asm("mov.b64 {%0, %1}, %2;" : "=f"(r0), "=f"(r1) : "l"(acc[p][c]));
                    int col = lane + 32 * c;
                    if (gr0 < SEG)     out[(size_t)gr0 * D + col]       = r0 + bb[c];
                    if (gr0 + 1 < SEG) out[(size_t)(gr0 + 1) * D + col] = r1 + bb[c];
                }
            }
            __syncthreads();   // protect As/Bs before next item
        }
    }
}

// ---------------------------------------------------------------------------
// Launch pipeline: hist_rank -> scan(+reset) -> perm -> persistent(reduce+gemm)
// Inputs (metadata order): src[f32 NE*D], index[i32 NE], W[f32 D*2D], b[f32 D]
// ---------------------------------------------------------------------------
extern "C" void kernel_launch(void* const* d_in, const int* in_sizes, int n_in,
                              void* d_out, int out_size) {
    const float* src   = (const float*)d_in[0];
    const int*   index = (const int*)d_in[1];
    const float* W     = (const float*)d_in[2];
    const float* bias  = (const float*)d_in[3];
    float* out = (float*)d_out;

    (void)in_sizes; (void)n_in; (void)out_size;

    hist_rank_kernel<<<(NE / 8 + 255) / 256, 256>>>(index);
    scan_kernel<<<1, 1024>>>();
    perm_kernel<<<(NE / 8 + 255) / 256, 256>>>(index);
    persistent_kernel<<<592, 256>>>(src, W, bias, out);   // 4 blocks/SM x 148 SMs
}

// round 9
// speedup vs baseline: 1.0655x; 1.0084x over previous
#include <cuda_runtime.h>
#include <cstdint>

// Problem constants (fixed by the dataset)
#define NE     1600000
#define D      128
#define TWO_D  256
#define SEG    50000

#define NEG_INF __int_as_float(0xFF800000)

// Scratch: device globals (no cudaMalloc allowed). Zero at module load;
// scan_kernel re-zeroes g_cnt each replay (it runs earlier in stream order
// than its consumers).
static __device__ int   g_cnt[SEG];                 // histogram (self-cleaning)
static __device__ int   g_offs[SEG + 1];            // exclusive offsets
static __device__ int   g_rank[NE];                 // per-edge rank within segment
static __device__ int   g_perm[NE];                 // edge ids grouped by segment
static __device__ float g_cat[(size_t)SEG * TWO_D]; // [seg][0:128)=sum, [128:256)=max

// ---------------------------------------------------------------------------
// Kernel 1: fused histogram + rank, 8 edges per thread.
// ---------------------------------------------------------------------------
__global__ void __launch_bounds__(256) hist_rank_kernel(const int* __restrict__ index) {
    int i = blockIdx.x * 256 + threadIdx.x;          // unit: 2 x int4 = 8 edges
    if (i < NE / 8) {
        int4 s0 = ((const int4*)index)[2 * i];
        int4 s1 = ((const int4*)index)[2 * i + 1];
        int4 r0, r1;
        r0.x = atomicAdd(&g_cnt[s0.x], 1);
        r0.y = atomicAdd(&g_cnt[s0.y], 1);
        r0.z = atomicAdd(&g_cnt[s0.z], 1);
        r0.w = atomicAdd(&g_cnt[s0.w], 1);
        r1.x = atomicAdd(&g_cnt[s1.x], 1);
        r1.y = atomicAdd(&g_cnt[s1.y], 1);
        r1.z = atomicAdd(&g_cnt[s1.z], 1);
        r1.w = atomicAdd(&g_cnt[s1.w], 1);
        ((int4*)g_rank)[2 * i]     = r0;
        ((int4*)g_rank)[2 * i + 1] = r1;
    }
}

// ---------------------------------------------------------------------------
// Kernel 2: exclusive scan of 50K counters — spill-free (no per-thread local
// array). Two global passes over L2-hot counters + 1024-wide smem scan.
// Also zeroes g_cnt for the next graph replay.
// ---------------------------------------------------------------------------
__global__ void __launch_bounds__(1024) scan_kernel() {
    __shared__ int part[1024];
    const int CH = 49;                     // 1024*49 = 50176 >= 50000
    int t = threadIdx.x;

    int lo = t * CH; if (lo > SEG) lo = SEG;
    int hi = lo + CH; if (hi > SEG) hi = SEG;

    // pass 1: per-thread sum, unrolled predicated loads (high MLP, no spill)
    int s = 0;
    #pragma unroll
    for (int j = 0; j < CH; j++) {
        int idx = lo + j;
        if (idx < hi) s += g_cnt[idx];
    }
    part[t] = s;
    __syncthreads();

    // inclusive Hillis-Steele scan over 1024 partials
    for (int off = 1; off < 1024; off <<= 1) {
        int v = 0;
        if (t >= off) v = part[t - off];
        __syncthreads();
        if (t >= off) part[t] += v;
        __syncthreads();
    }

    // pass 2: re-read counters (L2-hot), emit offsets, zero counters
    int run = (t == 0) ? 0 : part[t - 1];
    for (int i = lo; i < hi; i++) {
        int c = g_cnt[i];
        g_offs[i] = run;
        g_cnt[i]  = 0;                     // self-clean for next replay
        run += c;
    }
    if (t == 1023) g_offs[SEG] = part[1023];
}

// ---------------------------------------------------------------------------
// Kernel 3: atomic-free permutation scatter, 8 edges per thread.
// ---------------------------------------------------------------------------
__global__ void __launch_bounds__(256) perm_kernel(const int* __restrict__ index) {
    int i = blockIdx.x * 256 + threadIdx.x;
    if (i < NE / 8) {
        int4 s0 = ((const int4*)index)[2 * i];
        int4 s1 = ((const int4*)index)[2 * i + 1];
        int4 r0 = ((const int4*)g_rank)[2 * i];
        int4 r1 = ((const int4*)g_rank)[2 * i + 1];
        int e = i * 8;
        g_perm[__ldg(&g_offs[s0.x]) + r0.x] = e;
        g_perm[__ldg(&g_offs[s0.y]) + r0.y] = e + 1;
        g_perm[__ldg(&g_offs[s0.z]) + r0.z] = e + 2;
        g_perm[__ldg(&g_offs[s0.w]) + r0.w] = e + 3;
        g_perm[__ldg(&g_offs[s1.x]) + r1.x] = e + 4;
        g_perm[__ldg(&g_offs[s1.y]) + r1.y] = e + 5;
        g_perm[__ldg(&g_offs[s1.z]) + r1.z] = e + 6;
        g_perm[__ldg(&g_offs[s1.w]) + r1.w] = e + 7;
    }
}

// ---------------------------------------------------------------------------
// Kernel 4: segment reduce (lean: 32 regs, max occupancy — measured at the
// LTS/HBM cap, 6.27 TB/s). One warp per segment; lane owns 4 features;
// unroll x8 for MLP. Empty segments -> max = 0.
// ---------------------------------------------------------------------------
__global__ void __launch_bounds__(256) reduce_kernel(const float* __restrict__ src) {
    int seg  = blockIdx.x * 8 + (threadIdx.x >> 5);
    int lane = threadIdx.x & 31;
    if (seg >= SEG) return;

    int start = __ldg(&g_offs[seg]);
    int end   = __ldg(&g_offs[seg + 1]);

    float4 sum = make_float4(0.f, 0.f, 0.f, 0.f);
    float4 mx  = make_float4(NEG_INF, NEG_INF, NEG_INF, NEG_INF);

    int i = start;
    for (; i + 7 < end; i += 8) {
        int e[8];
        #pragma unroll
        for (int j = 0; j < 8; j++) e[j] = __ldg(&g_perm[i + j]);
        float4 v[8];
        #pragma unroll
        for (int j = 0; j < 8; j++)
            v[j] = __ldcs((const float4*)(src + (size_t)e[j] * D) + lane);
        #pragma unroll
        for (int j = 0; j < 8; j++) {
            sum.x += v[j].x; sum.y += v[j].y; sum.z += v[j].z; sum.w += v[j].w;
            mx.x = fmaxf(mx.x, v[j].x); mx.y = fmaxf(mx.y, v[j].y);
            mx.z = fmaxf(mx.z, v[j].z); mx.w = fmaxf(mx.w, v[j].w);
        }
    }
    for (; i < end; i++) {
        int e0 = __ldg(&g_perm[i]);
        float4 v0 = __ldcs((const float4*)(src + (size_t)e0 * D) + lane);
        sum.x += v0.x; sum.y += v0.y; sum.z += v0.z; sum.w += v0.w;
        mx.x = fmaxf(mx.x, v0.x); mx.y = fmaxf(mx.y, v0.y);
        mx.z = fmaxf(mx.z, v0.z); mx.w = fmaxf(mx.w, v0.w);
    }

    if (start == end)                 // torch_scatter: empty max = 0
        mx = make_float4(0.f, 0.f, 0.f, 0.f);

    size_t base = (size_t)seg * TWO_D + (size_t)lane * 4;
    *(float4*)(g_cat + base)     = sum;
    *(float4*)(g_cat + base + D) = mx;
}

// ---------------------------------------------------------------------------
// Kernel 5: out[n, d] = sum_k g_cat[n, k] * W[d, k] + b[d]
// Row-pair-packed FFMA2 GEMM, zero MOVs in the hot loop (measured-best shape).
// ---------------------------------------------------------------------------
#define BM   128
#define BK   16
#define AMS  132   // As row stride (words)
#define BS2S 258   // Bs row stride (words, duplicated layout)

__global__ void __launch_bounds__(256) gemm_kernel(const float* __restrict__ W,
                                                   const float* __restrict__ bias,
                                                   float* __restrict__ out) {
    __shared__ float As[BK * AMS];     // As[k][m]
    __shared__ float Bs[BK * BS2S];    // Bs[k][2d] = Bs[k][2d+1] = W[d][k]

    int tid  = threadIdx.x;
    int w    = tid >> 5;    // rows 16w .. 16w+15
    int lane = tid & 31;    // cols lane + 32c
    int row0 = blockIdx.x * BM;

    unsigned long long acc[8][4];   // [row pair p][col c]
    #pragma unroll
    for (int p = 0; p < 8; p++)
        #pragma unroll
        for (int c = 0; c < 4; c++) acc[p][c] = 0ull;

    for (int kc = 0; kc < TWO_D; kc += BK) {
        #pragma unroll
        for (int l = 0; l < 2; l++) {
            int idx = tid + l * 256;
            int m   = idx >> 2;          // 0..127
            int k4  = (idx & 3) * 4;     // 0,4,8,12
            int gr  = row0 + m;
            float4 v = make_float4(0.f, 0.f, 0.f, 0.f);
            if (gr < SEG)
                v = *(const float4*)(g_cat + (size_t)gr * TWO_D + kc + k4);
            As[(k4 + 0) * AMS + m] = v.x;
            As[(k4 + 1) * AMS + m] = v.y;
            As[(k4 + 2) * AMS + m] = v.z;
            As[(k4 + 3) * AMS + m] = v.w;
        }
        #pragma unroll
        for (int l = 0; l < 2; l++) {
            int idx = tid + l * 256;
            int d   = idx >> 2;          // 0..127
            int k4  = (idx & 3) * 4;
            float4 v = *(const float4*)(W + (size_t)d * TWO_D + kc + k4);
            float vv[4] = {v.x, v.y, v.z, v.w};
            #pragma unroll
            for (int q = 0; q < 4; q++) {
                unsigned long long dup;
                asm("mov.b64 %0, {%1, %1};" : "=l"(dup) : "f"(vv[q]));
                *(unsigned long long*)(Bs + (k4 + q) * BS2S + 2 * d) = dup;
            }
        }
        __syncthreads();

        #pragma unroll
        for (int k = 0; k < BK; k++) {
            unsigned long long ap[8];
            #pragma unroll
            for (int g = 0; g < 4; g++) {
                ulonglong2 a2 = *(const ulonglong2*)(As + k * AMS + 16 * w + 4 * g);
                ap[2 * g]     = a2.x;
                ap[2 * g + 1] = a2.y;
            }
            unsigned long long bsr[4];
            #pragma unroll
            for (int c = 0; c < 4; c++)
                bsr[c] = *(const unsigned long long*)(Bs + k * BS2S + 2 * (lane + 32 * c));

            #pragma unroll
            for (int p = 0; p < 8; p++)
                #pragma unroll
                for (int c = 0; c < 4; c++)
                    asm("fma.rn.f32x2 %0, %1, %2, %0;"
                        : "+l"(acc[p][c]) : "l"(ap[p]), "l"(bsr[c]));
        }
        __syncthreads();
    }

    float bb[4];
    #pragma unroll
    for (int c = 0; c < 4; c++) bb[c] = __ldg(bias + lane + 32 * c);

    #pragma unroll
    for (int p = 0; p < 8; p++) {
        int gr0 = row0 + 16 * w + 2 * p;
        #pragma unroll
        for (int c = 0; c < 4; c++) {
            float r0, r1;
            asm("mov.b64 {%0, %1}, %2;" : "=f"(r0), "=f"(r1) : "l"(acc[p][c]));
            int col = lane + 32 * c;
            if (gr0 < SEG)     out[(size_t)gr0 * D + col]       = r0 + bb[c];
            if (gr0 + 1 < SEG) out[(size_t)(gr0 + 1) * D + col] = r1 + bb[c];
        }
    }
}

// ---------------------------------------------------------------------------
// Launch pipeline: hist_rank -> scan(+clean) -> perm -> reduce -> gemm
// Inputs (metadata order): src[f32 NE*D], index[i32 NE], W[f32 D*2D], b[f32 D]
// ---------------------------------------------------------------------------
extern "C" void kernel_launch(void* const* d_in, const int* in_sizes, int n_in,
                              void* d_out, int out_size) {
    const float* src   = (const float*)d_in[0];
    const int*   index = (const int*)d_in[1];
    const float* W     = (const float*)d_in[2];
    const float* bias  = (const float*)d_in[3];
    float* out = (float*)d_out;

    (void)in_sizes; (void)n_in; (void)out_size;

    hist_rank_kernel<<<(NE / 8 + 255) / 256, 256>>>(index);
    scan_kernel<<<1, 1024>>>();
    perm_kernel<<<(NE / 8 + 255) / 256, 256>>>(index);
    reduce_kernel<<<SEG / 8, 256>>>(src);
    gemm_kernel<<<(SEG + BM - 1) / BM, 256>>>(W, bias, out);
}

// round 10
// speedup vs baseline: 1.2565x; 1.1793x over previous
#include <cuda_runtime.h>
#include <cstdint>

// Problem constants (fixed by the dataset)
#define NE     1600000
#define D      128
#define TWO_D  256
#define SEG    50000

#define NEG_INF __int_as_float(0xFF800000)

#define SCAN_BLOCKS 196   // ceil(50000 / 256)

// Scratch: device globals (no cudaMalloc allowed). Zero at module load;
// scan_local re-zeroes g_cnt each replay (runs before its next producer use).
static __device__ int   g_cnt[SEG];                 // histogram (self-cleaning)
static __device__ int   g_offs[SEG + 1];            // block-local exclusive offsets
static __device__ int   g_bsum[SCAN_BLOCKS];        // per-scan-block totals
static __device__ int   g_bpre[SCAN_BLOCKS];        // exclusive prefix of block totals
static __device__ int   g_rank[NE];                 // per-edge rank within segment
static __device__ int   g_perm[NE];                 // edge ids grouped by segment
static __device__ float g_cat[(size_t)SEG * TWO_D]; // [seg][0:128)=sum, [128:256)=max

// ---------------------------------------------------------------------------
// Kernel 1: fused histogram + rank, 8 edges per thread.
// ---------------------------------------------------------------------------
__global__ void __launch_bounds__(256) hist_rank_kernel(const int* __restrict__ index) {
    int i = blockIdx.x * 256 + threadIdx.x;          // unit: 2 x int4 = 8 edges
    if (i < NE / 8) {
        int4 s0 = ((const int4*)index)[2 * i];
        int4 s1 = ((const int4*)index)[2 * i + 1];
        int4 r0, r1;
        r0.x = atomicAdd(&g_cnt[s0.x], 1);
        r0.y = atomicAdd(&g_cnt[s0.y], 1);
        r0.z = atomicAdd(&g_cnt[s0.z], 1);
        r0.w = atomicAdd(&g_cnt[s0.w], 1);
        r1.x = atomicAdd(&g_cnt[s1.x], 1);
        r1.y = atomicAdd(&g_cnt[s1.y], 1);
        r1.z = atomicAdd(&g_cnt[s1.z], 1);
        r1.w = atomicAdd(&g_cnt[s1.w], 1);
        ((int4*)g_rank)[2 * i]     = r0;
        ((int4*)g_rank)[2 * i + 1] = r1;
    }
}

// ---------------------------------------------------------------------------
// Kernel 2: parallel block-local exclusive scan. 196 blocks x 256 threads;
// block b scans counters [256b, 256b+256), writes local-exclusive offsets,
// the block total, and zeroes the counters it consumed (replay-clean).
// ---------------------------------------------------------------------------
__global__ void __launch_bounds__(256) scan_local_kernel() {
    __shared__ int s[256];
    int t = threadIdx.x;
    int i = blockIdx.x * 256 + t;

    int c = (i < SEG) ? g_cnt[i] : 0;
    if (i < SEG) g_cnt[i] = 0;             // self-clean for next replay
    s[t] = c;
    __syncthreads();

    // inclusive Hillis-Steele over 256 entries
    #pragma unroll
    for (int off = 1; off < 256; off <<= 1) {
        int v = 0;
        if (t >= off) v = s[t - off];
        __syncthreads();
        if (t >= off) s[t] += v;
        __syncthreads();
    }

    if (i <= SEG) g_offs[i] = s[t] - c;    // exclusive within block
    if (t == 255) g_bsum[blockIdx.x] = s[255];
}

// ---------------------------------------------------------------------------
// Kernel 3: tiny top-level scan of 196 block totals (one block).
// ---------------------------------------------------------------------------
__global__ void __launch_bounds__(256) scan_top_kernel() {
    __shared__ int s[256];
    int t = threadIdx.x;
    int c = (t < SCAN_BLOCKS) ? g_bsum[t] : 0;
    s[t] = c;
    __syncthreads();
    #pragma unroll
    for (int off = 1; off < 256; off <<= 1) {
        int v = 0;
        if (t >= off) v = s[t - off];
        __syncthreads();
        if (t >= off) s[t] += v;
        __syncthreads();
    }
    if (t < SCAN_BLOCKS) g_bpre[t] = s[t] - c;   // exclusive prefix
}

// offs(seg) = g_offs[seg] + g_bpre[seg >> 8]
__device__ __forceinline__ int seg_off(int seg) {
    return __ldg(&g_offs[seg]) + __ldg(&g_bpre[seg >> 8]);
}

// ---------------------------------------------------------------------------
// Kernel 4: atomic-free permutation scatter, 8 edges per thread.
// ---------------------------------------------------------------------------
__global__ void __launch_bounds__(256) perm_kernel(const int* __restrict__ index) {
    int i = blockIdx.x * 256 + threadIdx.x;
    if (i < NE / 8) {
        int4 s0 = ((const int4*)index)[2 * i];
        int4 s1 = ((const int4*)index)[2 * i + 1];
        int4 r0 = ((const int4*)g_rank)[2 * i];
        int4 r1 = ((const int4*)g_rank)[2 * i + 1];
        int e = i * 8;
        g_perm[seg_off(s0.x) + r0.x] = e;
        g_perm[seg_off(s0.y) + r0.y] = e + 1;
        g_perm[seg_off(s0.z) + r0.z] = e + 2;
        g_perm[seg_off(s0.w) + r0.w] = e + 3;
        g_perm[seg_off(s1.x) + r1.x] = e + 4;
        g_perm[seg_off(s1.y) + r1.y] = e + 5;
        g_perm[seg_off(s1.z) + r1.z] = e + 6;
        g_perm[seg_off(s1.w) + r1.w] = e + 7;
    }
}

// ---------------------------------------------------------------------------
// Kernel 5: segment reduce (lean 32 regs, max occupancy — measured at the
// LTS/HBM cap). One warp per segment; lane owns 4 features; unroll x8.
// Empty segments -> max = 0.
// ---------------------------------------------------------------------------
__global__ void __launch_bounds__(256) reduce_kernel(const float* __restrict__ src) {
    int seg  = blockIdx.x * 8 + (threadIdx.x >> 5);
    int lane = threadIdx.x & 31;
    if (seg >= SEG) return;

    int start = seg_off(seg);
    int end   = seg_off(seg + 1);

    float4 sum = make_float4(0.f, 0.f, 0.f, 0.f);
    float4 mx  = make_float4(NEG_INF, NEG_INF, NEG_INF, NEG_INF);

    int i = start;
    for (; i + 7 < end; i += 8) {
        int e[8];
        #pragma unroll
        for (int j = 0; j < 8; j++) e[j] = __ldg(&g_perm[i + j]);
        float4 v[8];
        #pragma unroll
        for (int j = 0; j < 8; j++)
            v[j] = __ldcs((const float4*)(src + (size_t)e[j] * D) + lane);
        #pragma unroll
        for (int j = 0; j < 8; j++) {
            sum.x += v[j].x; sum.y += v[j].y; sum.z += v[j].z; sum.w += v[j].w;
            mx.x = fmaxf(mx.x, v[j].x); mx.y = fmaxf(mx.y, v[j].y);
            mx.z = fmaxf(mx.z, v[j].z); mx.w = fmaxf(mx.w, v[j].w);
        }
    }
    for (; i < end; i++) {
        int e0 = __ldg(&g_perm[i]);
        float4 v0 = __ldcs((const float4*)(src + (size_t)e0 * D) + lane);
        sum.x += v0.x; sum.y += v0.y; sum.z += v0.z; sum.w += v0.w;
        mx.x = fmaxf(mx.x, v0.x); mx.y = fmaxf(mx.y, v0.y);
        mx.z = fmaxf(mx.z, v0.z); mx.w = fmaxf(mx.w, v0.w);
    }

    if (start == end)                 // torch_scatter: empty max = 0
        mx = make_float4(0.f, 0.f, 0.f, 0.f);

    size_t base = (size_t)seg * TWO_D + (size_t)lane * 4;
    *(float4*)(g_cat + base)     = sum;
    *(float4*)(g_cat + base + D) = mx;
}

// ---------------------------------------------------------------------------
// Kernel 6: out[n, d] = sum_k g_cat[n, k] * W[d, k] + b[d]
// Row-pair-packed FFMA2 GEMM (zero hot-loop MOVs), BM=64 at 4 blocks/SM for
// better wave shape (782 blocks / 592 concurrent).
// ---------------------------------------------------------------------------
#define BM   64
#define BK   16
#define AMS  68    // As row stride (words): 64 + 4 pad
#define BS2S 258   // Bs row stride (words, duplicated layout)

__global__ void __launch_bounds__(256, 4) gemm_kernel(const float* __restrict__ W,
                                                      const float* __restrict__ bias,
                                                      float* __restrict__ out) {
    __shared__ float As[BK * AMS];     // As[k][m], m in [0,64)
    __shared__ float Bs[BK * BS2S];    // Bs[k][2d] = Bs[k][2d+1] = W[d][k]

    int tid  = threadIdx.x;
    int w    = tid >> 5;    // rows 8w .. 8w+7
    int lane = tid & 31;    // cols lane + 32c
    int row0 = blockIdx.x * BM;

    unsigned long long acc[4][4];   // [row pair p][col c]
    #pragma unroll
    for (int p = 0; p < 4; p++)
        #pragma unroll
        for (int c = 0; c < 4; c++) acc[p][c] = 0ull;

    for (int kc = 0; kc < TWO_D; kc += BK) {
        // stage A: 64 m x 16 k = 256 float4, 1 per thread
        {
            int m  = tid >> 2;           // 0..63
            int k4 = (tid & 3) * 4;      // 0,4,8,12
            int gr = row0 + m;
            float4 v = make_float4(0.f, 0.f, 0.f, 0.f);
            if (gr < SEG)
                v = *(const float4*)(g_cat + (size_t)gr * TWO_D + kc + k4);
            As[(k4 + 0) * AMS + m] = v.x;
            As[(k4 + 1) * AMS + m] = v.y;
            As[(k4 + 2) * AMS + m] = v.z;
            As[(k4 + 3) * AMS + m] = v.w;
        }
        // stage B duplicated: 128 d x 16 k = 512 float4, 2 per thread
        #pragma unroll
        for (int l = 0; l < 2; l++) {
            int idx = tid + l * 256;
            int d   = idx >> 2;          // 0..127
            int k4  = (idx & 3) * 4;
            float4 v = *(const float4*)(W + (size_t)d * TWO_D + kc + k4);
            float vv[4] = {v.x, v.y, v.z, v.w};
            #pragma unroll
            for (int q = 0; q < 4; q++) {
                unsigned long long dup;
                asm("mov.b64 %0, {%1, %1};" : "=l"(dup) : "f"(vv[q]));
                *(unsigned long long*)(Bs + (k4 + q) * BS2S + 2 * d) = dup;
            }
        }
        __syncthreads();

        #pragma unroll
        for (int k = 0; k < BK; k++) {
            unsigned long long ap[4];
            #pragma unroll
            for (int g = 0; g < 2; g++) {
                ulonglong2 a2 = *(const ulonglong2*)(As + k * AMS + 8 * w + 4 * g);
                ap[2 * g]     = a2.x;
                ap[2 * g + 1] = a2.y;
            }
            unsigned long long bsr[4];
            #pragma unroll
            for (int c = 0; c < 4; c++)
                bsr[c] = *(const unsigned long long*)(Bs + k * BS2S + 2 * (lane + 32 * c));

            #pragma unroll
            for (int p = 0; p < 4; p++)
                #pragma unroll
                for (int c = 0; c < 4; c++)
                    asm("fma.rn.f32x2 %0, %1, %2, %0;"
                        : "+l"(acc[p][c]) : "l"(ap[p]), "l"(bsr[c]));
        }
        __syncthreads();
    }

    float bb[4];
    #pragma unroll
    for (int c = 0; c < 4; c++) bb[c] = __ldg(bias + lane + 32 * c);

    #pragma unroll
    for (int p = 0; p < 4; p++) {
        int gr0 = row0 + 8 * w + 2 * p;
        #pragma unroll
        for (int c = 0; c < 4; c++) {
            float r0, r1;
            asm("mov.b64 {%0, %1}, %2;" : "=f"(r0), "=f"(r1) : "l"(acc[p][c]));
            int col = lane + 32 * c;
            if (gr0 < SEG)     out[(size_t)gr0 * D + col]       = r0 + bb[c];
            if (gr0 + 1 < SEG) out[(size_t)(gr0 + 1) * D + col] = r1 + bb[c];
        }
    }
}

// ---------------------------------------------------------------------------
// Launch pipeline:
//   hist_rank -> scan_local -> scan_top -> perm -> reduce -> gemm
// Inputs (metadata order): src[f32 NE*D], index[i32 NE], W[f32 D*2D], b[f32 D]
// ---------------------------------------------------------------------------
extern "C" void kernel_launch(void* const* d_in, const int* in_sizes, int n_in,
                              void* d_out, int out_size) {
    const float* src   = (const float*)d_in[0];
    const int*   index = (const int*)d_in[1];
    const float* W     = (const float*)d_in[2];
    const float* bias  = (const float*)d_in[3];
    float* out = (float*)d_out;

    (void)in_sizes; (void)n_in; (void)out_size;

    hist_rank_kernel<<<(NE / 8 + 255) / 256, 256>>>(index);
    scan_local_kernel<<<SCAN_BLOCKS, 256>>>();
    scan_top_kernel<<<1, 256>>>();
    perm_kernel<<<(NE / 8 + 255) / 256, 256>>>(index);
    reduce_kernel<<<SEG / 8, 256>>>(src);
    gemm_kernel<<<(SEG + BM - 1) / BM, 256>>>(W, bias, out);
}